// round 6
// baseline (speedup 1.0000x reference)
#include <cuda_runtime.h>

// Sizes: x (256,4096) f32, weights (64,64,64) f32, out (256,4096) f32.
// out[b, f*64+n] = sum_c sum_m w[f,c,m] * x[b, c*64 + (n-m) mod 64]
// computed in the 64-point DFT domain with rfft symmetry (33 freqs).

#define NF 33
#define BSZ 256
#define CC 64
#define FF 64

// [k][row] planes. Wf rows = f*64+c (4096), Xf rows = b*64+c (16384),
// S rows = b*64+f (16384).
__device__ float2 g_Wf[NF * FF * CC];
__device__ float2 g_Xf[NF * BSZ * CC];
__device__ float2 g_S [NF * BSZ * FF];

// ---------------------------------------------------------------------------
// Kernel 1: forward rDFT of every length-64 row (4096 w-rows + 16384 x-rows).
// Radix-2 split: e[j] = v[j]+v[j+32], o[j] = v[j]-v[j+32];
//   X[k] = sum_{j<32} (k even ? e[j] : o[j]) * tw[(j*k)&63],  k = 0..31
//   X[32] = sum_j (-1)^j e[j]  (computed in the staging phase via shuffles).
// e/o stored TRANSPOSED [j][row] (pitch 136 -> conflict-free stage writes,
// float4-able compute reads). CTA = 128 rows (16 warps x 8 rows), 160 CTAs.
// Inner loop per j: 2 x LDS.128 (broadcast) + 1 x LDS.64 + 16 FMA.
// ---------------------------------------------------------------------------
__global__ void __launch_bounds__(512) k_dft(const float* __restrict__ x,
                                             const float* __restrict__ w) {
    __shared__ float  esm[32][136];
    __shared__ float  osm[32][136];
    __shared__ float2 Bsm[32][32];    // [j][k]
    __shared__ float2 tw[64];

    const int t = threadIdx.x;
    if (t < 64) {
        float s, c;
        sincospif(-(float)t * (1.0f / 32.0f), &s, &c);
        tw[t] = make_float2(c, s);
    }
    __syncthreads();
#pragma unroll
    for (int i = t; i < 1024; i += 512) {
        const int j = i >> 5, k = i & 31;
        Bsm[j][k] = tw[(j * k) & 63];
    }

    const int row0 = blockIdx.x * 128;
    const bool isW = row0 < FF * CC;          // 4096 = 32 CTAs * 128, clean split
    const float* src = isW ? (w + row0 * 64) : (x + (row0 - FF * CC) * 64);
    float2* base = isW ? g_Wf : g_Xf;
    const int plane = isW ? (FF * CC) : (BSZ * CC);
    const int roff = isW ? row0 : (row0 - FF * CC);

    // ---- stage: radix-2 pre-sums + k=32 parity sum ----
    {
        const int r = t >> 2, q = t & 3;     // 4 threads per row
        const float4* s4 = (const float4*)(src + r * 64);
        float psum = 0.0f;
#pragma unroll
        for (int h = 0; h < 2; h++) {
            const int g = q + 4 * h;         // float4 index in first half
            const float4 a  = s4[g];
            const float4 bq = s4[g + 8];
            const float e0 = a.x + bq.x, e1 = a.y + bq.y;
            const float e2 = a.z + bq.z, e3 = a.w + bq.w;
            esm[4 * g + 0][r] = e0;  osm[4 * g + 0][r] = a.x - bq.x;
            esm[4 * g + 1][r] = e1;  osm[4 * g + 1][r] = a.y - bq.y;
            esm[4 * g + 2][r] = e2;  osm[4 * g + 2][r] = a.z - bq.z;
            esm[4 * g + 3][r] = e3;  osm[4 * g + 3][r] = a.w - bq.w;
            psum += e0 - e1 + e2 - e3;       // j = 4g even start
        }
        psum += __shfl_xor_sync(0xffffffffu, psum, 1);
        psum += __shfl_xor_sync(0xffffffffu, psum, 2);
        if (q == 0) base[32 * plane + roff + r] = make_float2(psum, 0.0f);
    }
    __syncthreads();

    // ---- compute: warp = 8 rows, lane = frequency k ----
    const int warp = t >> 5, lane = t & 31;
    const int r0 = warp * 8;
    const float (*usm)[136] = (lane & 1) ? osm : esm;

    float ar[8] = {}, ai[8] = {};
#pragma unroll 8
    for (int j = 0; j < 32; j++) {
        const float2 b = Bsm[j][lane];
        const float4 vA = *(const float4*)&usm[j][r0];
        const float4 vB = *(const float4*)&usm[j][r0 + 4];
        ar[0] = fmaf(vA.x, b.x, ar[0]);  ai[0] = fmaf(vA.x, b.y, ai[0]);
        ar[1] = fmaf(vA.y, b.x, ar[1]);  ai[1] = fmaf(vA.y, b.y, ai[1]);
        ar[2] = fmaf(vA.z, b.x, ar[2]);  ai[2] = fmaf(vA.z, b.y, ai[2]);
        ar[3] = fmaf(vA.w, b.x, ar[3]);  ai[3] = fmaf(vA.w, b.y, ai[3]);
        ar[4] = fmaf(vB.x, b.x, ar[4]);  ai[4] = fmaf(vB.x, b.y, ai[4]);
        ar[5] = fmaf(vB.y, b.x, ar[5]);  ai[5] = fmaf(vB.y, b.y, ai[5]);
        ar[6] = fmaf(vB.z, b.x, ar[6]);  ai[6] = fmaf(vB.z, b.y, ai[6]);
        ar[7] = fmaf(vB.w, b.x, ar[7]);  ai[7] = fmaf(vB.w, b.y, ai[7]);
    }

    // lane k writes rows r0..r0+7 at its k-plane: 4 x STG.128 (64 B run)
    float2* dst = base + lane * plane + roff + r0;
    float4* dst4 = (float4*)dst;
#pragma unroll
    for (int u = 0; u < 4; u++)
        dst4[u] = make_float4(ar[2 * u], ai[2 * u], ar[2 * u + 1], ai[2 * u + 1]);
}

// ---------------------------------------------------------------------------
// Kernel 2: per-frequency complex GEMM, Karatsuba 3-mult form.
// Grid (4 b-tiles, 33 freqs), 512 thr. Tile 64b x 64f over 64 c; thread =
// 2b x 4f. Operands packed float4 (re, im, re+im, 0) in smem so the 3-term
// accumulate needs the same 6 LDS.128/c as the 4-term version.
//   Re = a1 - a2,  Im = a3 - a1 - a2
// ---------------------------------------------------------------------------
__global__ void __launch_bounds__(512) k_gemm() {
    extern __shared__ float4 sm4[];
    float4* Xs = sm4;            // [64][64]   (b-major, pitch 64)
    float4* Ws = sm4 + 64 * 64;  // [64][65]   (f-major, pitch 65)

    const int k  = blockIdx.y;
    const int b0 = blockIdx.x * 64;
    const float2* gX = g_Xf + k * (BSZ * CC) + b0 * CC;
    const float2* gW = g_Wf + k * (FF * CC);

#pragma unroll
    for (int i = threadIdx.x; i < 4096; i += 512) {
        const float2 xv = gX[i];
        Xs[i] = make_float4(xv.x, xv.y, xv.x + xv.y, 0.0f);
        const float2 wv = gW[i];
        Ws[(i >> 6) * 65 + (i & 63)] = make_float4(wv.x, wv.y, wv.x + wv.y, 0.0f);
    }
    __syncthreads();

    const int tf = threadIdx.x & 15;   // f = tf + 16*i
    const int tb = threadIdx.x >> 4;   // b = tb + 32*j

    float a1[2][4] = {}, a2[2][4] = {}, a3[2][4] = {};
#pragma unroll 4
    for (int c = 0; c < 64; c++) {
        float4 xv[2], wv[4];
#pragma unroll
        for (int j = 0; j < 2; j++) xv[j] = Xs[(tb + 32 * j) * 64 + c];
#pragma unroll
        for (int i = 0; i < 4; i++) wv[i] = Ws[(tf + 16 * i) * 65 + c];
#pragma unroll
        for (int j = 0; j < 2; j++)
#pragma unroll
            for (int i = 0; i < 4; i++) {
                a1[j][i] = fmaf(xv[j].x, wv[i].x, a1[j][i]);
                a2[j][i] = fmaf(xv[j].y, wv[i].y, a2[j][i]);
                a3[j][i] = fmaf(xv[j].z, wv[i].z, a3[j][i]);
            }
    }

    float2* gS = g_S + k * (BSZ * FF) + b0 * FF;
#pragma unroll
    for (int j = 0; j < 2; j++)
#pragma unroll
        for (int i = 0; i < 4; i++) {
            const float re = a1[j][i] - a2[j][i];
            const float im = a3[j][i] - a1[j][i] - a2[j][i];
            gS[(tb + 32 * j) * FF + (tf + 16 * i)] = make_float2(re, im);
        }
}

// ---------------------------------------------------------------------------
// Kernel 3: real inverse transform with n / n+32 symmetry:
//   out[r][n]    = E[r][n] + O[r][n]
//   out[r][n+32] = E[r][n] - O[r][n]      (n < 32)
//   E over even k, O over odd k, Bm[k][n] = (s_k cos, -s_k sin),
//   s_k = 1/64 for k in {0,32} else 2/64.
// CTA = 128 rows x 512 thr -> 128 CTAs (single wave). Bm read as float4.
// ---------------------------------------------------------------------------
__global__ void __launch_bounds__(512) k_inv(float* __restrict__ out) {
    __shared__ float2 Ssh[128][NF];  // [row][k]
    __shared__ float2 Bm[NF][32];    // n < 32 only
    __shared__ float2 tw[64];

    const int t = threadIdx.x;
    if (t < 64) {
        float s, c;
        sincospif((float)t * (1.0f / 32.0f), &s, &c);
        tw[t] = make_float2(c, s);
    }
    __syncthreads();
#pragma unroll
    for (int i = t; i < NF * 32; i += 512) {
        const int k = i >> 5, n = i & 31;
        const float sc = (k == 0 || k == 32) ? (1.0f / 64.0f) : (2.0f / 64.0f);
        const float2 wv = tw[(k * n) & 63];
        Bm[k][n] = make_float2(sc * wv.x, -sc * wv.y);
    }

    const int r0 = blockIdx.x * 128;
#pragma unroll
    for (int i = t; i < 128 * NF; i += 512) {
        const int rl = i & 127, k = i >> 7;
        Ssh[rl][k] = g_S[k * (BSZ * FF) + r0 + rl];
    }
    __syncthreads();

    const int ng  = t & 3;    // n = ng*8 .. ng*8+7 (lower half)
    const int row = t >> 2;   // 0..127

    float e[8] = {}, o[8] = {};
#pragma unroll
    for (int kk = 0; kk < 17; kk++) {          // even k = 0,2,...,32
        const int k = 2 * kk;
        const float2 sv = Ssh[row][k];
        const float4* b4 = (const float4*)Bm[k] + ng * 4;
#pragma unroll
        for (int u = 0; u < 4; u++) {
            const float4 b = b4[u];
            e[2 * u + 0] = fmaf(sv.x, b.x, e[2 * u + 0]);
            e[2 * u + 0] = fmaf(sv.y, b.y, e[2 * u + 0]);
            e[2 * u + 1] = fmaf(sv.x, b.z, e[2 * u + 1]);
            e[2 * u + 1] = fmaf(sv.y, b.w, e[2 * u + 1]);
        }
    }
#pragma unroll
    for (int kk = 0; kk < 16; kk++) {          // odd k = 1,3,...,31
        const int k = 2 * kk + 1;
        const float2 sv = Ssh[row][k];
        const float4* b4 = (const float4*)Bm[k] + ng * 4;
#pragma unroll
        for (int u = 0; u < 4; u++) {
            const float4 b = b4[u];
            o[2 * u + 0] = fmaf(sv.x, b.x, o[2 * u + 0]);
            o[2 * u + 0] = fmaf(sv.y, b.y, o[2 * u + 0]);
            o[2 * u + 1] = fmaf(sv.x, b.z, o[2 * u + 1]);
            o[2 * u + 1] = fmaf(sv.y, b.w, o[2 * u + 1]);
        }
    }

    float* obase = out + (r0 + row) * 64 + ng * 8;
    float4* olo = (float4*)obase;
    float4* ohi = (float4*)(obase + 32);
    olo[0] = make_float4(e[0] + o[0], e[1] + o[1], e[2] + o[2], e[3] + o[3]);
    olo[1] = make_float4(e[4] + o[4], e[5] + o[5], e[6] + o[6], e[7] + o[7]);
    ohi[0] = make_float4(e[0] - o[0], e[1] - o[1], e[2] - o[2], e[3] - o[3]);
    ohi[1] = make_float4(e[4] - o[4], e[5] - o[5], e[6] - o[6], e[7] - o[7]);
}

// ---------------------------------------------------------------------------
extern "C" void kernel_launch(void* const* d_in, const int* in_sizes, int n_in,
                              void* d_out, int out_size) {
    const float* x = (const float*)d_in[0];
    const float* w = (const float*)d_in[1];
    // Defensive: identify by element count (x = 1048576, w = 262144).
    if (n_in >= 2 && in_sizes[0] == 64 * 64 * 64) {
        x = (const float*)d_in[1];
        w = (const float*)d_in[0];
    }

    static const size_t gemm_smem = (64 * 64 + 64 * 65) * sizeof(float4); // 132096
    cudaFuncSetAttribute(k_gemm, cudaFuncAttributeMaxDynamicSharedMemorySize,
                         (int)gemm_smem);

    // 20480 rows total (4096 weight rows + 16384 x rows), 128 rows per CTA.
    k_dft<<<160, 512>>>(x, w);
    k_gemm<<<dim3(4, 33), 512, gemm_smem>>>();
    k_inv<<<128, 512>>>((float*)d_out);
}

// round 7
// speedup vs baseline: 1.2369x; 1.2369x over previous
#include <cuda_runtime.h>

// Sizes: x (256,4096) f32, weights (64,64,64) f32, out (256,4096) f32.
// out[b, f*64+n] = sum_c sum_m w[f,c,m] * x[b, c*64 + (n-m) mod 64]
// computed in the 64-point DFT domain with rfft symmetry (33 freqs).

#define NF 33
#define BSZ 256
#define CC 64
#define FF 64

// [k][row] planes. Wf rows = f*64+c (4096), Xf rows = b*64+c (16384),
// S rows = b*64+f (16384).
__device__ float2 g_Wf[NF * FF * CC];
__device__ float2 g_Xf[NF * BSZ * CC];
__device__ float2 g_S [NF * BSZ * FF];

// ---------------------------------------------------------------------------
// Kernel 1: forward rDFT of every length-64 row (4096 w-rows + 16384 x-rows).
// Radix-2: e[j] = v[j]+v[j+32], o[j] = v[j]-v[j+32];
//   X[k] = sum_{j<32} (k even ? e[j] : o[j]) * tw[(j*k)&63],  k = 0..31
//   X[32] = sum_j (-1)^j e[j].
// e/o stored transposed [j][row], pitch 32. Stage: warp w owns float4-column
// w (lane = row) -> store bank = lane, conflict-free. Compute: warp = 4 rows,
// lane = k; per j: 1 broadcast LDS.128 + 1 LDS.64 + 8 FMA.
// CTA = 32 rows x 256 thr, grid 640 (4096 w-rows = first 128 CTAs exactly).
// ---------------------------------------------------------------------------
__global__ void __launch_bounds__(256) k_dft(const float* __restrict__ x,
                                             const float* __restrict__ w) {
    __shared__ float  esm[32][32];    // [j][row]
    __shared__ float  osm[32][32];
    __shared__ float  psm[8][32];     // per-warp partial parity sums
    __shared__ float2 Bsm[32][32];    // [j][k]
    __shared__ float2 tw[64];

    const int t = threadIdx.x;
    const int warp = t >> 5, lane = t & 31;

    if (t < 64) {
        float s, c;
        sincospif(-(float)t * (1.0f / 32.0f), &s, &c);
        tw[t] = make_float2(c, s);
    }
    __syncthreads();
#pragma unroll
    for (int i = t; i < 1024; i += 256) {
        const int j = i >> 5, k = i & 31;
        Bsm[j][k] = tw[(j * k) & 63];
    }

    const int row0 = blockIdx.x * 32;
    const bool isW = row0 < FF * CC;
    const float* src = isW ? (w + row0 * 64) : (x + (row0 - FF * CC) * 64);
    float2* base = isW ? g_Wf : g_Xf;
    const int plane = isW ? (FF * CC) : (BSZ * CC);
    const int roff = isW ? row0 : (row0 - FF * CC);

    // ---- stage: warp w handles columns j = 4w..4w+3, lane = row ----
    {
        const float4* s4 = (const float4*)src;    // row r = float4s [16r..16r+16)
        const float4 a  = s4[lane * 16 + warp];
        const float4 bq = s4[lane * 16 + warp + 8];
        const float e0 = a.x + bq.x, e1 = a.y + bq.y;
        const float e2 = a.z + bq.z, e3 = a.w + bq.w;
        esm[4 * warp + 0][lane] = e0;  osm[4 * warp + 0][lane] = a.x - bq.x;
        esm[4 * warp + 1][lane] = e1;  osm[4 * warp + 1][lane] = a.y - bq.y;
        esm[4 * warp + 2][lane] = e2;  osm[4 * warp + 2][lane] = a.z - bq.z;
        esm[4 * warp + 3][lane] = e3;  osm[4 * warp + 3][lane] = a.w - bq.w;
        psm[warp][lane] = e0 - e1 + e2 - e3;      // j = 4w even start
    }
    __syncthreads();

    // ---- k = 32 plane (threads 0..31) ----
    if (t < 32) {
        float p = 0.0f;
#pragma unroll
        for (int wq = 0; wq < 8; wq++) p += psm[wq][t];
        base[32 * plane + roff + t] = make_float2(p, 0.0f);
    }

    // ---- compute: warp = 4 rows, lane = frequency k ----
    const int r0 = warp * 4;
    const float (*usm)[32] = (lane & 1) ? osm : esm;

    float ar[4] = {}, ai[4] = {};
#pragma unroll 8
    for (int j = 0; j < 32; j++) {
        const float2 b = Bsm[j][lane];
        const float4 v = *(const float4*)&usm[j][r0];
        ar[0] = fmaf(v.x, b.x, ar[0]);  ai[0] = fmaf(v.x, b.y, ai[0]);
        ar[1] = fmaf(v.y, b.x, ar[1]);  ai[1] = fmaf(v.y, b.y, ai[1]);
        ar[2] = fmaf(v.z, b.x, ar[2]);  ai[2] = fmaf(v.z, b.y, ai[2]);
        ar[3] = fmaf(v.w, b.x, ar[3]);  ai[3] = fmaf(v.w, b.y, ai[3]);
    }

    // lane k writes rows r0..r0+3 at its k-plane: 2 x STG.128
    float4* dst4 = (float4*)(base + lane * plane + roff + r0);
    dst4[0] = make_float4(ar[0], ai[0], ar[1], ai[1]);
    dst4[1] = make_float4(ar[2], ai[2], ar[3], ai[3]);
}

// ---------------------------------------------------------------------------
// Kernel 2: per-frequency complex GEMM, Karatsuba 3-mult with SEPARATE sum
// arrays (float, conflict-free strides). Grid (4 b-tiles, 33 freqs), 256 thr.
// Tile 64b x 64f over 64 c; thread = 4b x 4f -> 48 FMA per c against
// ~15 LDS phases per warp per c => FMA-bound.
//   Re = a1 - a2,  Im = a3 - a1 - a2
// ---------------------------------------------------------------------------
__global__ void __launch_bounds__(256) k_gemm() {
    extern __shared__ float smf[];
    float2* Xs   = (float2*)smf;                    // [64][64]
    float*  Xsum = smf + 2 * 4096;                  // [64][64]
    float2* Ws   = (float2*)(smf + 3 * 4096);       // [64][65]
    float*  Wsum = smf + 3 * 4096 + 2 * 64 * 65;    // [64][65]

    const int k  = blockIdx.y;
    const int b0 = blockIdx.x * 64;
    const float2* gX = g_Xf + k * (BSZ * CC) + b0 * CC;
    const float2* gW = g_Wf + k * (FF * CC);

#pragma unroll
    for (int i = threadIdx.x; i < 4096; i += 256) {
        const float2 xv = gX[i];
        Xs[i] = xv;
        Xsum[i] = xv.x + xv.y;
        const float2 wv = gW[i];
        const int p = (i >> 6) * 65 + (i & 63);
        Ws[p] = wv;
        Wsum[p] = wv.x + wv.y;
    }
    __syncthreads();

    const int tf = threadIdx.x & 15;   // f = tf + 16*i
    const int tb = threadIdx.x >> 4;   // b = tb + 16*j

    float a1[4][4] = {}, a2[4][4] = {}, a3[4][4] = {};
#pragma unroll 2
    for (int c = 0; c < 64; c++) {
        float2 xv[4], wv[4];
        float  xs[4], ws[4];
#pragma unroll
        for (int j = 0; j < 4; j++) {
            xv[j] = Xs[(tb + 16 * j) * 64 + c];
            xs[j] = Xsum[(tb + 16 * j) * 64 + c];
        }
#pragma unroll
        for (int i = 0; i < 4; i++) {
            wv[i] = Ws[(tf + 16 * i) * 65 + c];
            ws[i] = Wsum[(tf + 16 * i) * 65 + c];
        }
#pragma unroll
        for (int j = 0; j < 4; j++)
#pragma unroll
            for (int i = 0; i < 4; i++) {
                a1[j][i] = fmaf(xv[j].x, wv[i].x, a1[j][i]);
                a2[j][i] = fmaf(xv[j].y, wv[i].y, a2[j][i]);
                a3[j][i] = fmaf(xs[j],   ws[i],   a3[j][i]);
            }
    }

    float2* gS = g_S + k * (BSZ * FF) + b0 * FF;
#pragma unroll
    for (int j = 0; j < 4; j++)
#pragma unroll
        for (int i = 0; i < 4; i++) {
            const float re = a1[j][i] - a2[j][i];
            const float im = a3[j][i] - a1[j][i] - a2[j][i];
            gS[(tb + 16 * j) * FF + (tf + 16 * i)] = make_float2(re, im);
        }
}

// ---------------------------------------------------------------------------
// Kernel 3: real inverse transform with n / n+32 symmetry:
//   out[r][n]    = E[r][n] + O[r][n]
//   out[r][n+32] = E[r][n] - O[r][n]      (n < 32)
//   E over even k, O over odd k, Bm[k][n] = (s_k cos, -s_k sin),
//   s_k = 1/64 for k in {0,32} else 2/64.
// CTA = 64 rows, thread = (row, 8-wide n-group in lower half). 256 CTAs.
// ---------------------------------------------------------------------------
__global__ void __launch_bounds__(256) k_inv(float* __restrict__ out) {
    __shared__ float2 Ssh[64][NF];   // [row][k]
    __shared__ float2 Bm[NF][32];    // n < 32 only
    __shared__ float2 tw[64];

    const int t = threadIdx.x;
    if (t < 64) {
        float s, c;
        sincospif((float)t * (1.0f / 32.0f), &s, &c);
        tw[t] = make_float2(c, s);
    }
    __syncthreads();
#pragma unroll
    for (int i = t; i < NF * 32; i += 256) {
        const int k = i >> 5, n = i & 31;
        const float sc = (k == 0 || k == 32) ? (1.0f / 64.0f) : (2.0f / 64.0f);
        const float2 wv = tw[(k * n) & 63];
        Bm[k][n] = make_float2(sc * wv.x, -sc * wv.y);
    }

    const int r0 = blockIdx.x * 64;
#pragma unroll
    for (int i = t; i < 64 * NF; i += 256) {
        const int rl = i & 63, k = i >> 6;
        Ssh[rl][k] = g_S[k * (BSZ * FF) + r0 + rl];
    }
    __syncthreads();

    const int ng  = t & 3;    // n = ng*8 .. ng*8+7 (lower half)
    const int row = t >> 2;   // 0..63

    float e[8] = {}, o[8] = {};
#pragma unroll
    for (int kk = 0; kk < 17; kk++) {          // even k = 0,2,...,32
        const int k = 2 * kk;
        const float2 sv = Ssh[row][k];
#pragma unroll
        for (int u = 0; u < 8; u++) {
            const float2 b = Bm[k][ng * 8 + u];
            e[u] = fmaf(sv.x, b.x, e[u]);
            e[u] = fmaf(sv.y, b.y, e[u]);
        }
    }
#pragma unroll
    for (int kk = 0; kk < 16; kk++) {          // odd k = 1,3,...,31
        const int k = 2 * kk + 1;
        const float2 sv = Ssh[row][k];
#pragma unroll
        for (int u = 0; u < 8; u++) {
            const float2 b = Bm[k][ng * 8 + u];
            o[u] = fmaf(sv.x, b.x, o[u]);
            o[u] = fmaf(sv.y, b.y, o[u]);
        }
    }

    float* obase = out + (r0 + row) * 64 + ng * 8;
    float4* olo = (float4*)obase;
    float4* ohi = (float4*)(obase + 32);
    olo[0] = make_float4(e[0] + o[0], e[1] + o[1], e[2] + o[2], e[3] + o[3]);
    olo[1] = make_float4(e[4] + o[4], e[5] + o[5], e[6] + o[6], e[7] + o[7]);
    ohi[0] = make_float4(e[0] - o[0], e[1] - o[1], e[2] - o[2], e[3] - o[3]);
    ohi[1] = make_float4(e[4] - o[4], e[5] - o[5], e[6] - o[6], e[7] - o[7]);
}

// ---------------------------------------------------------------------------
extern "C" void kernel_launch(void* const* d_in, const int* in_sizes, int n_in,
                              void* d_out, int out_size) {
    const float* x = (const float*)d_in[0];
    const float* w = (const float*)d_in[1];
    // Defensive: identify by element count (x = 1048576, w = 262144).
    if (n_in >= 2 && in_sizes[0] == 64 * 64 * 64) {
        x = (const float*)d_in[1];
        w = (const float*)d_in[0];
    }

    // Xs 32K + Xsum 16K + Ws 33.28K + Wsum 16.64K = 99072 bytes
    static const size_t gemm_smem =
        (3 * 4096 + 3 * 64 * 65) * sizeof(float);
    cudaFuncSetAttribute(k_gemm, cudaFuncAttributeMaxDynamicSharedMemorySize,
                         (int)gemm_smem);

    // 20480 rows total (4096 weight rows + 16384 x rows), 32 rows per CTA.
    k_dft<<<640, 256>>>(x, w);
    k_gemm<<<dim3(4, 33), 256, gemm_smem>>>();
    k_inv<<<256, 256>>>((float*)d_out);
}

// round 8
// speedup vs baseline: 1.2527x; 1.0127x over previous
#include <cuda_runtime.h>

// Sizes: x (256,4096) f32, weights (64,64,64) f32, out (256,4096) f32.
// out[b, f*64+n] = sum_c sum_m w[f,c,m] * x[b, c*64 + (n-m) mod 64]
// computed in the 64-point DFT domain with rfft symmetry (33 freqs).

#define NF 33
#define BSZ 256
#define CC 64
#define FF 64

// [k][row] planes. Wf rows = f*64+c (4096), Xf rows = b*64+c (16384),
// S rows = b*64+f (16384).
__device__ float2 g_Wf[NF * FF * CC];
__device__ float2 g_Xf[NF * BSZ * CC];
__device__ float2 g_S [NF * BSZ * FF];

// ---------------------------------------------------------------------------
// Kernel 1: forward rDFT of every length-64 row (4096 w-rows + 16384 x-rows).
// Radix-2: e[j] = v[j]+v[j+32], o[j] = v[j]-v[j+32];
//   X[k] = sum_{j<32} (k even ? e[j] : o[j]) * tw[(j*k)&63],  k = 0..31
//   X[32] = sum_j (-1)^j e[j].
// CTA = 64 rows x 256 thr, grid 320. Stage loads COALESCED (warp reads 128B
// runs); e/o transposed [j][row] pitch 68; compute warp = 8 rows, lane = k,
// per j: 2 broadcast LDS.128 + 1 LDS.64 + 16 FMA; outputs staged in outsm
// and stored COALESCED (256B-per-warp runs in each k plane).
// ---------------------------------------------------------------------------
__global__ void __launch_bounds__(256) k_dft(const float* __restrict__ x,
                                             const float* __restrict__ w) {
    __shared__ float  esm[32][68];    // [j][r]
    __shared__ float  osm[32][68];
    __shared__ float  psm[8][68];     // [hq][r] parity partials
    __shared__ float2 Bsm[32][32];    // [j][k]
    __shared__ float2 outsm[33][66];  // [k][r]
    __shared__ float2 tw[64];

    const int t = threadIdx.x;
    const int warp = t >> 5, lane = t & 31;

    if (t < 64) {
        float s, c;
        sincospif(-(float)t * (1.0f / 32.0f), &s, &c);
        tw[t] = make_float2(c, s);
    }
    __syncthreads();
#pragma unroll
    for (int i = t; i < 1024; i += 256) {
        const int j = i >> 5, k = i & 31;
        Bsm[j][k] = tw[(j * k) & 63];
    }

    const int row0 = blockIdx.x * 64;
    const bool isW = row0 < FF * CC;          // first 64 CTAs exactly
    const float* src = isW ? (w + row0 * 64) : (x + (row0 - FF * CC) * 64);
    float2* base = isW ? g_Wf : g_Xf;
    const int plane = isW ? (FF * CC) : (BSZ * CC);
    const int roff = isW ? row0 : (row0 - FF * CC);

    // ---- stage: thread = (row r / r+32, quarter hq); coalesced loads ----
    {
        const int r = t >> 3;        // 0..31
        const int hq = t & 7;
        const float4* s4 = (const float4*)src;
#pragma unroll
        for (int h = 0; h < 64; h += 32) {
            const int rr = r + h;
            const float4 a  = s4[rr * 16 + hq];
            const float4 bq = s4[rr * 16 + hq + 8];
            const float e0 = a.x + bq.x, e1 = a.y + bq.y;
            const float e2 = a.z + bq.z, e3 = a.w + bq.w;
            esm[4 * hq + 0][rr] = e0;  osm[4 * hq + 0][rr] = a.x - bq.x;
            esm[4 * hq + 1][rr] = e1;  osm[4 * hq + 1][rr] = a.y - bq.y;
            esm[4 * hq + 2][rr] = e2;  osm[4 * hq + 2][rr] = a.z - bq.z;
            esm[4 * hq + 3][rr] = e3;  osm[4 * hq + 3][rr] = a.w - bq.w;
            psm[hq][rr] = e0 - e1 + e2 - e3;   // j = 4hq starts even
        }
    }
    __syncthreads();

    // ---- k = 32 plane into outsm ----
    if (t < 64) {
        float p = 0.0f;
#pragma unroll
        for (int hq = 0; hq < 8; hq++) p += psm[hq][t];
        outsm[32][t] = make_float2(p, 0.0f);
    }

    // ---- compute: warp = 8 rows, lane = frequency k ----
    const int r0 = warp * 8;
    const float* ub = (lane & 1) ? &osm[0][0] : &esm[0][0];

    float ar[8] = {}, ai[8] = {};
#pragma unroll 4
    for (int j = 0; j < 32; j++) {
        const float2 b = Bsm[j][lane];
        const float4 vA = *(const float4*)(ub + j * 68 + r0);
        const float4 vB = *(const float4*)(ub + j * 68 + r0 + 4);
        ar[0] = fmaf(vA.x, b.x, ar[0]);  ai[0] = fmaf(vA.x, b.y, ai[0]);
        ar[1] = fmaf(vA.y, b.x, ar[1]);  ai[1] = fmaf(vA.y, b.y, ai[1]);
        ar[2] = fmaf(vA.z, b.x, ar[2]);  ai[2] = fmaf(vA.z, b.y, ai[2]);
        ar[3] = fmaf(vA.w, b.x, ar[3]);  ai[3] = fmaf(vA.w, b.y, ai[3]);
        ar[4] = fmaf(vB.x, b.x, ar[4]);  ai[4] = fmaf(vB.x, b.y, ai[4]);
        ar[5] = fmaf(vB.y, b.x, ar[5]);  ai[5] = fmaf(vB.y, b.y, ai[5]);
        ar[6] = fmaf(vB.z, b.x, ar[6]);  ai[6] = fmaf(vB.z, b.y, ai[6]);
        ar[7] = fmaf(vB.w, b.x, ar[7]);  ai[7] = fmaf(vB.w, b.y, ai[7]);
    }

    // stage results: lane k, rows r0..r0+7
    {
        float4* o4 = (float4*)&outsm[lane][r0];
#pragma unroll
        for (int u = 0; u < 4; u++)
            o4[u] = make_float4(ar[2 * u], ai[2 * u], ar[2 * u + 1], ai[2 * u + 1]);
    }
    __syncthreads();

    // ---- coalesced stores: warp writes 32 consecutive rows of one k ----
#pragma unroll
    for (int i = t; i < 33 * 64; i += 256) {
        const int k = i >> 6, rl = i & 63;
        base[k * plane + roff + rl] = outsm[k][rl];
    }
}

// ---------------------------------------------------------------------------
// Kernel 2: per-frequency complex GEMM, Karatsuba 3-mult, c-vectorized.
// Grid (4 b-tiles, 33 freqs), 256 thr. Tile 64b x 64f over 64 c; thread =
// 4b x 4f, c unrolled by 2 -> all operand loads are LDS.128/LDS.64.
//   Re = a1 - a2,  Im = a3 - a1 - a2
// Layouts padded: Xs/Ws pitch 66 (float2), Xsum/Wsum pitch 68 (float).
// ---------------------------------------------------------------------------
__global__ void __launch_bounds__(256) k_gemm() {
    extern __shared__ float smf[];
    float2* Xs   = (float2*)smf;                       // [64][66]
    float*  Xsum = smf + 2 * 64 * 66;                  // [64][68]
    float2* Ws   = (float2*)(smf + 2 * 64 * 66 + 64 * 68);   // [64][66]
    float*  Wsum = smf + 4 * 64 * 66 + 64 * 68;        // [64][68]

    const int k  = blockIdx.y;
    const int b0 = blockIdx.x * 64;
    const float2* gX = g_Xf + k * (BSZ * CC) + b0 * CC;
    const float2* gW = g_Wf + k * (FF * CC);

#pragma unroll
    for (int i = threadIdx.x; i < 4096; i += 256) {
        const int r = i >> 6, c = i & 63;
        const float2 xv = gX[i];
        Xs[r * 66 + c] = xv;
        Xsum[r * 68 + c] = xv.x + xv.y;
        const float2 wv = gW[i];
        Ws[r * 66 + c] = wv;
        Wsum[r * 68 + c] = wv.x + wv.y;
    }
    __syncthreads();

    const int tf = threadIdx.x & 15;   // f = tf + 16*i
    const int tb = threadIdx.x >> 4;   // b = tb + 16*j

    float a1[4][4] = {}, a2[4][4] = {}, a3[4][4] = {};
#pragma unroll 4
    for (int c = 0; c < 64; c += 2) {
        float4 xv[4], wv[4];
        float2 xs[4], ws[4];
#pragma unroll
        for (int j = 0; j < 4; j++) {
            const int b = tb + 16 * j;
            xv[j] = *(const float4*)&Xs[b * 66 + c];      // 2 c-values
            xs[j] = *(const float2*)&Xsum[b * 68 + c];
        }
#pragma unroll
        for (int i = 0; i < 4; i++) {
            const int f = tf + 16 * i;
            wv[i] = *(const float4*)&Ws[f * 66 + c];
            ws[i] = *(const float2*)&Wsum[f * 68 + c];
        }
#pragma unroll
        for (int j = 0; j < 4; j++)
#pragma unroll
            for (int i = 0; i < 4; i++) {
                a1[j][i] = fmaf(xv[j].x, wv[i].x, a1[j][i]);
                a2[j][i] = fmaf(xv[j].y, wv[i].y, a2[j][i]);
                a3[j][i] = fmaf(xs[j].x, ws[i].x, a3[j][i]);
                a1[j][i] = fmaf(xv[j].z, wv[i].z, a1[j][i]);
                a2[j][i] = fmaf(xv[j].w, wv[i].w, a2[j][i]);
                a3[j][i] = fmaf(xs[j].y, ws[i].y, a3[j][i]);
            }
    }

    float2* gS = g_S + k * (BSZ * FF) + b0 * FF;
#pragma unroll
    for (int j = 0; j < 4; j++)
#pragma unroll
        for (int i = 0; i < 4; i++) {
            const float re = a1[j][i] - a2[j][i];
            const float im = a3[j][i] - a1[j][i] - a2[j][i];
            gS[(tb + 16 * j) * FF + (tf + 16 * i)] = make_float2(re, im);
        }
}

// ---------------------------------------------------------------------------
// Kernel 3: real inverse transform with n / n+32 symmetry:
//   out[r][n]    = E[r][n] + O[r][n]
//   out[r][n+32] = E[r][n] - O[r][n]      (n < 32)
//   E over even k, O over odd k, Bm[k][n] = (s_k cos, -s_k sin),
//   s_k = 1/64 for k in {0,32} else 2/64.
// CTA = 64 rows, thread = (row, 8-wide n-group in lower half). 256 CTAs.
// ---------------------------------------------------------------------------
__global__ void __launch_bounds__(256) k_inv(float* __restrict__ out) {
    __shared__ float2 Ssh[64][NF];   // [row][k]
    __shared__ float2 Bm[NF][32];    // n < 32 only
    __shared__ float2 tw[64];

    const int t = threadIdx.x;
    if (t < 64) {
        float s, c;
        sincospif((float)t * (1.0f / 32.0f), &s, &c);
        tw[t] = make_float2(c, s);
    }
    __syncthreads();
#pragma unroll
    for (int i = t; i < NF * 32; i += 256) {
        const int k = i >> 5, n = i & 31;
        const float sc = (k == 0 || k == 32) ? (1.0f / 64.0f) : (2.0f / 64.0f);
        const float2 wv = tw[(k * n) & 63];
        Bm[k][n] = make_float2(sc * wv.x, -sc * wv.y);
    }

    const int r0 = blockIdx.x * 64;
#pragma unroll
    for (int i = t; i < 64 * NF; i += 256) {
        const int rl = i & 63, k = i >> 6;
        Ssh[rl][k] = g_S[k * (BSZ * FF) + r0 + rl];
    }
    __syncthreads();

    const int ng  = t & 3;    // n = ng*8 .. ng*8+7 (lower half)
    const int row = t >> 2;   // 0..63

    float e[8] = {}, o[8] = {};
#pragma unroll
    for (int kk = 0; kk < 17; kk++) {          // even k = 0,2,...,32
        const int k = 2 * kk;
        const float2 sv = Ssh[row][k];
#pragma unroll
        for (int u = 0; u < 8; u++) {
            const float2 b = Bm[k][ng * 8 + u];
            e[u] = fmaf(sv.x, b.x, e[u]);
            e[u] = fmaf(sv.y, b.y, e[u]);
        }
    }
#pragma unroll
    for (int kk = 0; kk < 16; kk++) {          // odd k = 1,3,...,31
        const int k = 2 * kk + 1;
        const float2 sv = Ssh[row][k];
#pragma unroll
        for (int u = 0; u < 8; u++) {
            const float2 b = Bm[k][ng * 8 + u];
            o[u] = fmaf(sv.x, b.x, o[u]);
            o[u] = fmaf(sv.y, b.y, o[u]);
        }
    }

    float* obase = out + (r0 + row) * 64 + ng * 8;
    float4* olo = (float4*)obase;
    float4* ohi = (float4*)(obase + 32);
    olo[0] = make_float4(e[0] + o[0], e[1] + o[1], e[2] + o[2], e[3] + o[3]);
    olo[1] = make_float4(e[4] + o[4], e[5] + o[5], e[6] + o[6], e[7] + o[7]);
    ohi[0] = make_float4(e[0] - o[0], e[1] - o[1], e[2] - o[2], e[3] - o[3]);
    ohi[1] = make_float4(e[4] - o[4], e[5] - o[5], e[6] - o[6], e[7] - o[7]);
}

// ---------------------------------------------------------------------------
extern "C" void kernel_launch(void* const* d_in, const int* in_sizes, int n_in,
                              void* d_out, int out_size) {
    const float* x = (const float*)d_in[0];
    const float* w = (const float*)d_in[1];
    // Defensive: identify by element count (x = 1048576, w = 262144).
    if (n_in >= 2 && in_sizes[0] == 64 * 64 * 64) {
        x = (const float*)d_in[1];
        w = (const float*)d_in[0];
    }

    // Xs 33.8K + Xsum 17.4K + Ws 33.8K + Wsum 17.4K = 102400 bytes
    static const size_t gemm_smem =
        (4 * 64 * 66 + 2 * 64 * 68) * sizeof(float);
    cudaFuncSetAttribute(k_gemm, cudaFuncAttributeMaxDynamicSharedMemorySize,
                         (int)gemm_smem);

    // 20480 rows total (4096 weight rows + 16384 x rows), 64 rows per CTA.
    k_dft<<<320, 256>>>(x, w);
    k_gemm<<<dim3(4, 33), 256, gemm_smem>>>();
    k_inv<<<256, 256>>>((float*)d_out);
}